// round 10
// baseline (speedup 1.0000x reference)
#include <cuda_runtime.h>
#include <cuda_bf16.h>
#include <cstdint>

// ---------------- problem constants ----------------
#define BATCH 4
#define SQ    4096
#define SKV   4096
#define DIM   64
#define BM    128
#define BN    64
#define NT    (SKV / BN)
#define NTHREADS 512        // 16 warps: wq = w>>1 (16 q-rows), wn = w&1 (32 kv-cols)

// 4-stage K/V ring in dynamic smem: K stages at [0,32KB), V stages at [32KB,64KB)
#define SMEM_BYTES 65536

// log2(e)/8 folded into Q at staging -> S is in log2 domain
#define SCALE2 0.18033688011112042f

#define SW128(o) ((uint32_t)(o) ^ ((((uint32_t)(o)) >> 3) & 0x70u))

__device__ __forceinline__ uint32_t smem_u32(const void* p) {
    return (uint32_t)__cvta_generic_to_shared(p);
}
__device__ __forceinline__ void ldsm_x4(uint32_t& r0, uint32_t& r1, uint32_t& r2, uint32_t& r3, uint32_t a) {
    asm volatile("ldmatrix.sync.aligned.m8n8.x4.shared.b16 {%0,%1,%2,%3}, [%4];"
                 : "=r"(r0), "=r"(r1), "=r"(r2), "=r"(r3) : "r"(a));
}
__device__ __forceinline__ void ldsm_x4_t(uint32_t& r0, uint32_t& r1, uint32_t& r2, uint32_t& r3, uint32_t a) {
    asm volatile("ldmatrix.sync.aligned.m8n8.x4.trans.shared.b16 {%0,%1,%2,%3}, [%4];"
                 : "=r"(r0), "=r"(r1), "=r"(r2), "=r"(r3) : "r"(a));
}
__device__ __forceinline__ void mma_bf16(float* c, const uint32_t* a, uint32_t b0, uint32_t b1) {
    asm volatile("mma.sync.aligned.m16n8k16.row.col.f32.bf16.bf16.f32 "
                 "{%0,%1,%2,%3}, {%4,%5,%6,%7}, {%8,%9}, {%0,%1,%2,%3};"
                 : "+f"(c[0]), "+f"(c[1]), "+f"(c[2]), "+f"(c[3])
                 : "r"(a[0]), "r"(a[1]), "r"(a[2]), "r"(a[3]), "r"(b0), "r"(b1));
}
__device__ __forceinline__ float ex2f(float x) {
    float y; asm("ex2.approx.ftz.f32 %0, %1;" : "=f"(y) : "f"(x)); return y;
}
__device__ __forceinline__ uint32_t packbf2(float lo, float hi) {
    __nv_bfloat162 t = __floats2bfloat162_rn(lo, hi);
    return *reinterpret_cast<uint32_t*>(&t);
}
__device__ __forceinline__ float sigmoidf_(float x) {
    float e = ex2f(-x * 1.4426950408889634f);
    return 1.0f / (1.0f + e);
}
#define STS128(addr, a_, b_, c_, d_) \
    asm volatile("st.shared.v4.b32 [%0], {%1,%2,%3,%4};" \
                 :: "r"(addr), "r"(a_), "r"(b_), "r"(c_), "r"(d_))
#define LDS128(a_, b_, c_, d_, addr) \
    asm volatile("ld.shared.v4.b32 {%0,%1,%2,%3}, [%4];" \
                 : "=r"(a_), "=r"(b_), "=r"(c_), "=r"(d_) : "r"(addr))

__global__ __launch_bounds__(NTHREADS, 1)
void attn_fused_kernel(const float* __restrict__ gq,
                       const float* __restrict__ gk,
                       const float* __restrict__ gv,
                       float* __restrict__ gout) {
    // softmax denominators: [kv-half][row] (static smem)
    __shared__ __align__(16) float lpsh[2][BM];
    // dynamic smem: 4-stage K/V ring; first 16KB doubles as Q staging (pre-loop)
    // and O exchange (post-loop).
    extern __shared__ __align__(1024) __nv_bfloat16 sm_dyn[];

    const int tid = threadIdx.x;
    const int w   = tid >> 5;
    const int L   = tid & 31;
    const int wq  = w >> 1;      // q group: rows wq*16 .. wq*16+15
    const int wn  = w & 1;       // kv half: cols wn*32 .. wn*32+31
    const int b   = blockIdx.y;
    const int q0  = blockIdx.x * BM;

    const uint32_t dynB = smem_u32(sm_dyn);
    // stage s (0..3): K at dynB + s*8192, V at dynB + 32768 + s*8192

    // ---- Stage Q fp32 -> bf16 (pre-scaled), SW128 rows, in first 16KB ----
    {
        const int row  = tid >> 2;               // 0..127
        const int cblk = (tid & 3) * 16;         // 16 cols = 4 float4
        const float4* g = (const float4*)(gq + ((size_t)b * SQ + q0 + row) * DIM + cblk);
        float4 f0 = g[0], f1 = g[1], f2 = g[2], f3 = g[3];
        const uint32_t o0 = (uint32_t)(row * 128 + cblk * 2);
        STS128(dynB + SW128(o0),
               packbf2(f0.x * SCALE2, f0.y * SCALE2), packbf2(f0.z * SCALE2, f0.w * SCALE2),
               packbf2(f1.x * SCALE2, f1.y * SCALE2), packbf2(f1.z * SCALE2, f1.w * SCALE2));
        STS128(dynB + SW128(o0 + 16),
               packbf2(f2.x * SCALE2, f2.y * SCALE2), packbf2(f2.z * SCALE2, f2.w * SCALE2),
               packbf2(f3.x * SCALE2, f3.y * SCALE2), packbf2(f3.z * SCALE2, f3.w * SCALE2));
    }
    __syncthreads();

    // ---- Q fragments: 4 k-chunks of m16n8k16 A (16 regs) ----
    uint32_t aq[4][4];
    {
        const int rr = wq * 16 + ((L >> 3) & 1) * 8 + (L & 7);
        #pragma unroll
        for (int kc = 0; kc < 4; kc++) {
            const int cc = 16 * kc + (L >> 4) * 8;
            ldsm_x4(aq[kc][0], aq[kc][1], aq[kc][2], aq[kc][3],
                    dynB + SW128((uint32_t)(rr * 128 + cc * 2)));
        }
    }
    __syncthreads();   // Q staging consumed; region becomes K/V ring

    // ---- accumulators ----
    float oa[8][4];
    #pragma unroll
    for (int j = 0; j < 8; j++)
        #pragma unroll
        for (int i = 0; i < 4; i++) oa[j][i] = 0.0f;
    float lp0 = 0.0f, lp1 = 0.0f;

    // ---- gmem tile load mapping: 512 threads, each 8 floats of K and of V ----
    const int ldrow = tid >> 3;                  // 0..63
    const int ldcb  = (tid & 7) * 8;             // 8-col block
    const float4* gk4 = (const float4*)(gk + ((size_t)b * SKV + ldrow) * DIM + ldcb);
    const float4* gv4 = (const float4*)(gv + ((size_t)b * SKV + ldrow) * DIM + ldcb);
    const size_t tileF4 = (size_t)BN * DIM / 4;
    const uint32_t swT = SW128((uint32_t)(ldrow * 128 + ldcb * 2));

    float4 k0, k1, v0, v1;
    #define LOAD_TILE(t) do { const size_t _o = (size_t)(t) * tileF4;            \
        k0 = gk4[_o+0]; k1 = gk4[_o+1];                                          \
        v0 = gv4[_o+0]; v1 = gv4[_o+1]; } while(0)
    #define STORE_TILE(s) do {                                                   \
        STS128(dynB + (uint32_t)(s) * 8192u + swT,                               \
               packbf2(k0.x,k0.y), packbf2(k0.z,k0.w),                           \
               packbf2(k1.x,k1.y), packbf2(k1.z,k1.w));                          \
        STS128(dynB + 32768u + (uint32_t)(s) * 8192u + swT,                      \
               packbf2(v0.x,v0.y), packbf2(v0.z,v0.w),                           \
               packbf2(v1.x,v1.y), packbf2(v1.z,v1.w)); } while(0)

    // ldmatrix lane-address pieces
    const int kq_r  = (L & 7);
    const int kq_c8 = (L >> 3) * 8;
    const int v_r   = ((L >> 3) & 1) * 8 + (L & 7);
    const int v_c8  = (L >> 4) * 8;

    // ---- prologue: stage tiles 0,1; prefetch tile 2 into regs ----
    LOAD_TILE(0); STORE_TILE(0);
    LOAD_TILE(1); STORE_TILE(1);
    LOAD_TILE(2);

    // ---- main loop: barrier every 2 tiles (4-stage ring) ----
    // per step n: compute stage n&3; store tile n+2 into stage (n+2)&3; load tile n+3.
    #define TILE_BODY(n)                                                          \
    {                                                                             \
        const uint32_t skB = dynB + (uint32_t)((n) & 3) * 8192u;                  \
        const uint32_t svB = skB + 32768u;                                        \
        float sc[4][4];                                                           \
        _Pragma("unroll")                                                         \
        for (int j = 0; j < 4; j++) {                                             \
            _Pragma("unroll")                                                     \
            for (int i = 0; i < 4; i++) sc[j][i] = 0.0f;                          \
        }                                                                         \
        _Pragma("unroll")                                                         \
        for (int j = 0; j < 4; j++) {                                             \
            const int rr = wn * 32 + 8 * j + kq_r;                                \
            _Pragma("unroll")                                                     \
            for (int kc2 = 0; kc2 < 2; kc2++) {                                   \
                uint32_t b0, b1, b2, b3;                                          \
                const int cc = 32 * kc2 + kq_c8;                                  \
                ldsm_x4(b0, b1, b2, b3, skB + SW128((uint32_t)(rr * 128 + cc * 2))); \
                mma_bf16(sc[j], aq[2 * kc2],     b0, b1);                         \
                mma_bf16(sc[j], aq[2 * kc2 + 1], b2, b3);                         \
            }                                                                     \
        }                                                                         \
        uint32_t ap[2][4];                                                        \
        _Pragma("unroll")                                                         \
        for (int j = 0; j < 4; j++) {                                             \
            float p0 = ex2f(sc[j][0]);                                            \
            float p1 = ex2f(sc[j][1]);                                            \
            float p2 = ex2f(sc[j][2]);                                            \
            float p3 = ex2f(sc[j][3]);                                            \
            lp0 += p0 + p1;                                                       \
            lp1 += p2 + p3;                                                       \
            const int kcp = j >> 1;                                               \
            if (((j) & 1) == 0) {                                                 \
                ap[kcp][0] = packbf2(p0, p1);                                     \
                ap[kcp][1] = packbf2(p2, p3);                                     \
            } else {                                                              \
                ap[kcp][2] = packbf2(p0, p1);                                     \
                ap[kcp][3] = packbf2(p2, p3);                                     \
            }                                                                     \
        }                                                                         \
        if ((n) + 2 < NT) STORE_TILE(((n) + 2) & 3);                              \
        if ((n) + 3 < NT) LOAD_TILE((n) + 3);                                     \
        _Pragma("unroll")                                                         \
        for (int kcp = 0; kcp < 2; kcp++) {                                       \
            const int rr = wn * 32 + 16 * kcp + v_r;                              \
            _Pragma("unroll")                                                     \
            for (int j2 = 0; j2 < 8; j2 += 2) {                                   \
                uint32_t b0, b1, b2, b3;                                          \
                const int cc = 8 * j2 + v_c8;                                     \
                ldsm_x4_t(b0, b1, b2, b3, svB + SW128((uint32_t)(rr * 128 + cc * 2))); \
                mma_bf16(oa[j2],     ap[kcp], b0, b1);                            \
                mma_bf16(oa[j2 + 1], ap[kcp], b2, b3);                            \
            }                                                                     \
        }                                                                         \
    }

    for (int p = 0; p < NT / 2; p++) {
        __syncthreads();   // tiles 2p,2p+1 staged; stages of pair p-1 free
        const int n0 = 2 * p;
        TILE_BODY(n0);
        TILE_BODY(n0 + 1);
    }
    #undef TILE_BODY

    // ---- softmax denominators: quad-reduce; publish per (half,row) ----
    lp0 += __shfl_xor_sync(0xFFFFFFFFu, lp0, 1);
    lp0 += __shfl_xor_sync(0xFFFFFFFFu, lp0, 2);
    lp1 += __shfl_xor_sync(0xFFFFFFFFu, lp1, 1);
    lp1 += __shfl_xor_sync(0xFFFFFFFFu, lp1, 2);
    __syncthreads();   // all warps done with the ring
    if ((L & 3) == 0) {
        const int rbase = wq * 16 + (L >> 2);
        lpsh[wn][rbase]     = lp0;
        lpsh[wn][rbase + 8] = lp1;
    }

    // ---- O exchange: warp (wq,wn) keeps d-half wn, ships d-half 1-wn ----
    {
        const int ship = 1 - wn;
        const uint32_t slot = dynB + (uint32_t)(wq * 2 + ship) * 2048;
        #pragma unroll
        for (int jp = 0; jp < 4; jp++) {
            const int j = ship * 4 + jp;
            STS128(slot + (uint32_t)(jp * 32 + L) * 16,
                   __float_as_uint(oa[j][0]), __float_as_uint(oa[j][1]),
                   __float_as_uint(oa[j][2]), __float_as_uint(oa[j][3]));
        }
    }
    __syncthreads();
    {
        const uint32_t slot = dynB + (uint32_t)(wq * 2 + wn) * 2048;
        #pragma unroll
        for (int jp = 0; jp < 4; jp++) {
            const int j = wn * 4 + jp;
            uint32_t x, y, z, u;
            LDS128(x, y, z, u, slot + (uint32_t)(jp * 32 + L) * 16);
            oa[j][0] += __uint_as_float(x);
            oa[j][1] += __uint_as_float(y);
            oa[j][2] += __uint_as_float(z);
            oa[j][3] += __uint_as_float(u);
        }
    }

    // ---- epilogue: warp (wq,wn) owns rows wq*16+{0..15}, d-cols wn*32..+31 ----
    const int lr0 = wq * 16 + (L >> 2);
    const float inv0 = 1.0f / (lpsh[0][lr0] + lpsh[1][lr0]);
    const float inv1 = 1.0f / (lpsh[0][lr0 + 8] + lpsh[1][lr0 + 8]);

    const int r0 = q0 + lr0;
    const int r1 = r0 + 8;
    const float* q0p = gq + ((size_t)b * SQ + r0) * DIM;
    const float* q1p = gq + ((size_t)b * SQ + r1) * DIM;
    float* o0p = gout + ((size_t)b * SQ + r0) * DIM;
    float* o1p = gout + ((size_t)b * SQ + r1) * DIM;

    #pragma unroll
    for (int jp = 0; jp < 4; jp++) {
        const int j  = wn * 4 + jp;
        const int d0 = 8 * j + 2 * (L & 3);
        float2 qa = *(const float2*)(q0p + d0);
        float2 qb = *(const float2*)(q1p + d0);
        float o0 = oa[j][0] * inv0 + qa.x;
        float o1 = oa[j][1] * inv0 + qa.y;
        float o2 = oa[j][2] * inv1 + qb.x;
        float o3 = oa[j][3] * inv1 + qb.y;
        #pragma unroll
        for (int it = 0; it < 3; it++) {
            o0 = sigmoidf_(o0 + 2.0f * qa.x);
            o1 = sigmoidf_(o1 + 2.0f * qa.y);
            o2 = sigmoidf_(o2 + 2.0f * qb.x);
            o3 = sigmoidf_(o3 + 2.0f * qb.y);
            o0 = fminf(fmaxf(o0, 0.0f), 1.0f);
            o1 = fminf(fmaxf(o1, 0.0f), 1.0f);
            o2 = fminf(fmaxf(o2, 0.0f), 1.0f);
            o3 = fminf(fmaxf(o3, 0.0f), 1.0f);
        }
        *(float2*)(o0p + d0) = make_float2(o0, o1);
        *(float2*)(o1p + d0) = make_float2(o2, o3);
    }
}

extern "C" void kernel_launch(void* const* d_in, const int* in_sizes, int n_in,
                              void* d_out, int out_size) {
    const float* q = (const float*)d_in[0];
    const float* k = (const float*)d_in[1];
    const float* v = (const float*)d_in[2];
    float* out = (float*)d_out;

    // idempotent; needed for 64KB dynamic smem (static limit is 48KB)
    cudaFuncSetAttribute(attn_fused_kernel,
                         cudaFuncAttributeMaxDynamicSharedMemorySize, SMEM_BYTES);

    dim3 grid(SQ / BM, BATCH);
    attn_fused_kernel<<<grid, NTHREADS, SMEM_BYTES>>>(q, k, v, out);
}

// round 11
// speedup vs baseline: 1.5096x; 1.5096x over previous
#include <cuda_runtime.h>
#include <cuda_bf16.h>
#include <cstdint>

// ---------------- problem constants ----------------
#define BATCH 4
#define SQ    4096
#define SKV   4096
#define DIM   64
#define BM    128
#define BN    64
#define NT    (SKV / BN)
#define NTHREADS 512        // 16 warps: wq = w>>1 (16 q-rows), wn = w&1 (32 kv-cols)

// 4-stage K/V ring in dynamic smem: K stages at [0,32KB), V stages at [32KB,64KB)
#define SMEM_BYTES 65536

// log2(e)/8 folded into Q at staging -> S is in log2 domain
#define SCALE2 0.18033688011112042f

#define SW128(o) ((uint32_t)(o) ^ ((((uint32_t)(o)) >> 3) & 0x70u))

__device__ __forceinline__ uint32_t smem_u32(const void* p) {
    return (uint32_t)__cvta_generic_to_shared(p);
}
__device__ __forceinline__ void ldsm_x4(uint32_t& r0, uint32_t& r1, uint32_t& r2, uint32_t& r3, uint32_t a) {
    asm volatile("ldmatrix.sync.aligned.m8n8.x4.shared.b16 {%0,%1,%2,%3}, [%4];"
                 : "=r"(r0), "=r"(r1), "=r"(r2), "=r"(r3) : "r"(a));
}
__device__ __forceinline__ void ldsm_x4_t(uint32_t& r0, uint32_t& r1, uint32_t& r2, uint32_t& r3, uint32_t a) {
    asm volatile("ldmatrix.sync.aligned.m8n8.x4.trans.shared.b16 {%0,%1,%2,%3}, [%4];"
                 : "=r"(r0), "=r"(r1), "=r"(r2), "=r"(r3) : "r"(a));
}
__device__ __forceinline__ void mma_bf16(float* c, const uint32_t* a, uint32_t b0, uint32_t b1) {
    asm volatile("mma.sync.aligned.m16n8k16.row.col.f32.bf16.bf16.f32 "
                 "{%0,%1,%2,%3}, {%4,%5,%6,%7}, {%8,%9}, {%0,%1,%2,%3};"
                 : "+f"(c[0]), "+f"(c[1]), "+f"(c[2]), "+f"(c[3])
                 : "r"(a[0]), "r"(a[1]), "r"(a[2]), "r"(a[3]), "r"(b0), "r"(b1));
}
__device__ __forceinline__ float ex2f(float x) {
    float y; asm("ex2.approx.ftz.f32 %0, %1;" : "=f"(y) : "f"(x)); return y;
}
__device__ __forceinline__ uint32_t packbf2(float lo, float hi) {
    __nv_bfloat162 t = __floats2bfloat162_rn(lo, hi);
    return *reinterpret_cast<uint32_t*>(&t);
}
__device__ __forceinline__ float sigmoidf_(float x) {
    float e = ex2f(-x * 1.4426950408889634f);
    return 1.0f / (1.0f + e);
}
#define STS128(addr, a_, b_, c_, d_) \
    asm volatile("st.shared.v4.b32 [%0], {%1,%2,%3,%4};" \
                 :: "r"(addr), "r"(a_), "r"(b_), "r"(c_), "r"(d_))
#define LDS128(a_, b_, c_, d_, addr) \
    asm volatile("ld.shared.v4.b32 {%0,%1,%2,%3}, [%4];" \
                 : "=r"(a_), "=r"(b_), "=r"(c_), "=r"(d_) : "r"(addr))

__global__ __launch_bounds__(NTHREADS, 1)
void attn_fused_kernel(const float* __restrict__ gq,
                       const float* __restrict__ gk,
                       const float* __restrict__ gv,
                       float* __restrict__ gout) {
    // softmax denominators: [kv-half][row] (static smem)
    __shared__ __align__(16) float lpsh[2][BM];
    // dynamic smem: 4-stage K/V ring; first 16KB doubles as Q staging (pre-loop)
    // and O exchange (post-loop).
    extern __shared__ __align__(1024) __nv_bfloat16 sm_dyn[];

    const int tid = threadIdx.x;
    const int w   = tid >> 5;
    const int L   = tid & 31;
    const int wq  = w >> 1;      // q group: rows wq*16 .. wq*16+15
    const int wn  = w & 1;       // kv half: cols wn*32 .. wn*32+31
    const int b   = blockIdx.y;
    const int q0  = blockIdx.x * BM;

    const uint32_t dynB = smem_u32(sm_dyn);
    // stage s (0..3): K at dynB + s*8192, V at dynB + 32768 + s*8192

    // ---- Stage Q fp32 -> bf16 (pre-scaled), SW128 rows, in first 16KB ----
    {
        const int row  = tid >> 2;               // 0..127
        const int cblk = (tid & 3) * 16;         // 16 cols = 4 float4
        const float4* g = (const float4*)(gq + ((size_t)b * SQ + q0 + row) * DIM + cblk);
        float4 f0 = g[0], f1 = g[1], f2 = g[2], f3 = g[3];
        const uint32_t o0 = (uint32_t)(row * 128 + cblk * 2);
        STS128(dynB + SW128(o0),
               packbf2(f0.x * SCALE2, f0.y * SCALE2), packbf2(f0.z * SCALE2, f0.w * SCALE2),
               packbf2(f1.x * SCALE2, f1.y * SCALE2), packbf2(f1.z * SCALE2, f1.w * SCALE2));
        STS128(dynB + SW128(o0 + 16),
               packbf2(f2.x * SCALE2, f2.y * SCALE2), packbf2(f2.z * SCALE2, f2.w * SCALE2),
               packbf2(f3.x * SCALE2, f3.y * SCALE2), packbf2(f3.z * SCALE2, f3.w * SCALE2));
    }
    __syncthreads();

    // ---- Q fragments: 4 k-chunks of m16n8k16 A (16 regs) ----
    uint32_t aq[4][4];
    {
        const int rr = wq * 16 + ((L >> 3) & 1) * 8 + (L & 7);
        #pragma unroll
        for (int kc = 0; kc < 4; kc++) {
            const int cc = 16 * kc + (L >> 4) * 8;
            ldsm_x4(aq[kc][0], aq[kc][1], aq[kc][2], aq[kc][3],
                    dynB + SW128((uint32_t)(rr * 128 + cc * 2)));
        }
    }
    __syncthreads();   // Q staging consumed; region becomes K/V ring

    // ---- accumulators ----
    float oa[8][4];
    #pragma unroll
    for (int j = 0; j < 8; j++)
        #pragma unroll
        for (int i = 0; i < 4; i++) oa[j][i] = 0.0f;
    float lp0 = 0.0f, lp1 = 0.0f;

    // ---- gmem tile load mapping: 512 threads, each 8 floats of K and of V ----
    const int ldrow = tid >> 3;                  // 0..63
    const int ldcb  = (tid & 7) * 8;             // 8-col block
    const float4* gk4 = (const float4*)(gk + ((size_t)b * SKV + ldrow) * DIM + ldcb);
    const float4* gv4 = (const float4*)(gv + ((size_t)b * SKV + ldrow) * DIM + ldcb);
    const size_t tileF4 = (size_t)BN * DIM / 4;
    const uint32_t swT = SW128((uint32_t)(ldrow * 128 + ldcb * 2));

    float4 k0, k1, v0, v1;
    #define LOAD_TILE(t) do { const size_t _o = (size_t)(t) * tileF4;            \
        k0 = gk4[_o+0]; k1 = gk4[_o+1];                                          \
        v0 = gv4[_o+0]; v1 = gv4[_o+1]; } while(0)
    #define STORE_TILE(s) do {                                                   \
        STS128(dynB + (uint32_t)(s) * 8192u + swT,                               \
               packbf2(k0.x,k0.y), packbf2(k0.z,k0.w),                           \
               packbf2(k1.x,k1.y), packbf2(k1.z,k1.w));                          \
        STS128(dynB + 32768u + (uint32_t)(s) * 8192u + swT,                      \
               packbf2(v0.x,v0.y), packbf2(v0.z,v0.w),                           \
               packbf2(v1.x,v1.y), packbf2(v1.z,v1.w)); } while(0)

    // ldmatrix lane-address pieces
    const int kq_r  = (L & 7);
    const int kq_c8 = (L >> 3) * 8;
    const int v_r   = ((L >> 3) & 1) * 8 + (L & 7);
    const int v_c8  = (L >> 4) * 8;

    // ---- prologue: stage tiles 0,1; prefetch tile 2 into regs ----
    LOAD_TILE(0); STORE_TILE(0);
    LOAD_TILE(1); STORE_TILE(1);
    LOAD_TILE(2);

    // ---- main loop: single body (no duplication -> no spill), barrier every 2 tiles ----
    #pragma unroll 1
    for (int n = 0; n < NT; n++) {
        if ((n & 1) == 0) __syncthreads();   // tiles n, n+1 staged; pair n-2,n-1 stages free
        const uint32_t skB = dynB + (uint32_t)(n & 3) * 8192u;
        const uint32_t svB = skB + 32768u;

        // ---- S = Q @ K^T : 16q x 32kv per warp ----
        float sc[4][4];
        #pragma unroll
        for (int j = 0; j < 4; j++)
            #pragma unroll
            for (int i = 0; i < 4; i++) sc[j][i] = 0.0f;

        #pragma unroll
        for (int j = 0; j < 4; j++) {
            const int rr = wn * 32 + 8 * j + kq_r;
            #pragma unroll
            for (int kc2 = 0; kc2 < 2; kc2++) {
                uint32_t b0, b1, b2, b3;
                const int cc = 32 * kc2 + kq_c8;
                ldsm_x4(b0, b1, b2, b3, skB + SW128((uint32_t)(rr * 128 + cc * 2)));
                mma_bf16(sc[j], aq[2 * kc2],     b0, b1);
                mma_bf16(sc[j], aq[2 * kc2 + 1], b2, b3);
            }
        }

        // ---- softmax: p = 2^s; accumulate denominators; pack P as A-fragments ----
        uint32_t ap[2][4];
        #pragma unroll
        for (int j = 0; j < 4; j++) {
            float p0 = ex2f(sc[j][0]);
            float p1 = ex2f(sc[j][1]);
            float p2 = ex2f(sc[j][2]);
            float p3 = ex2f(sc[j][3]);
            lp0 += p0 + p1;
            lp1 += p2 + p3;
            const int kcp = j >> 1;
            if ((j & 1) == 0) {
                ap[kcp][0] = packbf2(p0, p1);
                ap[kcp][1] = packbf2(p2, p3);
            } else {
                ap[kcp][2] = packbf2(p0, p1);
                ap[kcp][3] = packbf2(p2, p3);
            }
        }

        // ---- stage traffic early: STS(n+2) drains during the O-phase MMA chain,
        //      LDG(n+3) latency hidden behind it; prefetch-reg lives stay short ----
        if (n + 2 < NT) STORE_TILE((n + 2) & 3);
        if (n + 3 < NT) LOAD_TILE(n + 3);

        // ---- O += P @ V : 16q x 64d per warp over its 32 kv rows ----
        #pragma unroll
        for (int kcp = 0; kcp < 2; kcp++) {
            const int rr = wn * 32 + 16 * kcp + v_r;
            #pragma unroll
            for (int j2 = 0; j2 < 8; j2 += 2) {
                uint32_t b0, b1, b2, b3;
                const int cc = 8 * j2 + v_c8;
                ldsm_x4_t(b0, b1, b2, b3, svB + SW128((uint32_t)(rr * 128 + cc * 2)));
                mma_bf16(oa[j2],     ap[kcp], b0, b1);
                mma_bf16(oa[j2 + 1], ap[kcp], b2, b3);
            }
        }
    }

    // ---- softmax denominators: quad-reduce; publish per (half,row) ----
    lp0 += __shfl_xor_sync(0xFFFFFFFFu, lp0, 1);
    lp0 += __shfl_xor_sync(0xFFFFFFFFu, lp0, 2);
    lp1 += __shfl_xor_sync(0xFFFFFFFFu, lp1, 1);
    lp1 += __shfl_xor_sync(0xFFFFFFFFu, lp1, 2);
    __syncthreads();   // all warps done with the ring
    if ((L & 3) == 0) {
        const int rbase = wq * 16 + (L >> 2);
        lpsh[wn][rbase]     = lp0;
        lpsh[wn][rbase + 8] = lp1;
    }

    // ---- O exchange: warp (wq,wn) keeps d-half wn, ships d-half 1-wn ----
    {
        const int ship = 1 - wn;
        const uint32_t slot = dynB + (uint32_t)(wq * 2 + ship) * 2048;
        #pragma unroll
        for (int jp = 0; jp < 4; jp++) {
            const int j = ship * 4 + jp;
            STS128(slot + (uint32_t)(jp * 32 + L) * 16,
                   __float_as_uint(oa[j][0]), __float_as_uint(oa[j][1]),
                   __float_as_uint(oa[j][2]), __float_as_uint(oa[j][3]));
        }
    }
    __syncthreads();
    {
        const uint32_t slot = dynB + (uint32_t)(wq * 2 + wn) * 2048;
        #pragma unroll
        for (int jp = 0; jp < 4; jp++) {
            const int j = wn * 4 + jp;
            uint32_t x, y, z, u;
            LDS128(x, y, z, u, slot + (uint32_t)(jp * 32 + L) * 16);
            oa[j][0] += __uint_as_float(x);
            oa[j][1] += __uint_as_float(y);
            oa[j][2] += __uint_as_float(z);
            oa[j][3] += __uint_as_float(u);
        }
    }

    // ---- epilogue: warp (wq,wn) owns rows wq*16+{0..15}, d-cols wn*32..+31 ----
    const int lr0 = wq * 16 + (L >> 2);
    const float inv0 = 1.0f / (lpsh[0][lr0] + lpsh[1][lr0]);
    const float inv1 = 1.0f / (lpsh[0][lr0 + 8] + lpsh[1][lr0 + 8]);

    const int r0 = q0 + lr0;
    const int r1 = r0 + 8;
    const float* q0p = gq + ((size_t)b * SQ + r0) * DIM;
    const float* q1p = gq + ((size_t)b * SQ + r1) * DIM;
    float* o0p = gout + ((size_t)b * SQ + r0) * DIM;
    float* o1p = gout + ((size_t)b * SQ + r1) * DIM;

    #pragma unroll
    for (int jp = 0; jp < 4; jp++) {
        const int j  = wn * 4 + jp;
        const int d0 = 8 * j + 2 * (L & 3);
        float2 qa = *(const float2*)(q0p + d0);
        float2 qb = *(const float2*)(q1p + d0);
        float o0 = oa[j][0] * inv0 + qa.x;
        float o1 = oa[j][1] * inv0 + qa.y;
        float o2 = oa[j][2] * inv1 + qb.x;
        float o3 = oa[j][3] * inv1 + qb.y;
        #pragma unroll
        for (int it = 0; it < 3; it++) {
            o0 = sigmoidf_(o0 + 2.0f * qa.x);
            o1 = sigmoidf_(o1 + 2.0f * qa.y);
            o2 = sigmoidf_(o2 + 2.0f * qb.x);
            o3 = sigmoidf_(o3 + 2.0f * qb.y);
            o0 = fminf(fmaxf(o0, 0.0f), 1.0f);
            o1 = fminf(fmaxf(o1, 0.0f), 1.0f);
            o2 = fminf(fmaxf(o2, 0.0f), 1.0f);
            o3 = fminf(fmaxf(o3, 0.0f), 1.0f);
        }
        *(float2*)(o0p + d0) = make_float2(o0, o1);
        *(float2*)(o1p + d0) = make_float2(o2, o3);
    }
}

extern "C" void kernel_launch(void* const* d_in, const int* in_sizes, int n_in,
                              void* d_out, int out_size) {
    const float* q = (const float*)d_in[0];
    const float* k = (const float*)d_in[1];
    const float* v = (const float*)d_in[2];
    float* out = (float*)d_out;

    // idempotent; needed for 64KB dynamic smem (static limit is 48KB)
    cudaFuncSetAttribute(attn_fused_kernel,
                         cudaFuncAttributeMaxDynamicSharedMemorySize, SMEM_BYTES);

    dim3 grid(SQ / BM, BATCH);
    attn_fused_kernel<<<grid, NTHREADS, SMEM_BYTES>>>(q, k, v, out);
}

// round 12
// speedup vs baseline: 2.0985x; 1.3901x over previous
#include <cuda_runtime.h>
#include <cuda_bf16.h>
#include <cstdint>

// ---------------- problem constants ----------------
#define BATCH 4
#define SQ    4096
#define SKV   4096
#define DIM   64
#define BM    128
#define BN    64
#define NT    (SKV / BN)
#define NTHREADS 512        // 16 warps: wq = w>>1 (16 q-rows), wn = w&1 (32 kv-cols)

// 4-stage K/V ring in dynamic smem: K stages at [0,32KB), V stages at [32KB,64KB)
#define SMEM_BYTES 65536

// log2(e)/8 folded into Q at staging -> S is in log2 domain
#define SCALE2 0.18033688011112042f

#define SW128(o) ((uint32_t)(o) ^ ((((uint32_t)(o)) >> 3) & 0x70u))

// ---------------- static scratch: pre-swizzled bf16 tile images ----------------
// tile (b,t): 8KB = 512 x uint4; image byte x == smem stage byte x (verbatim copy)
__device__ uint4 g_kbf[BATCH * NT * 512];
__device__ uint4 g_vbf[BATCH * NT * 512];

__device__ __forceinline__ uint32_t smem_u32(const void* p) {
    return (uint32_t)__cvta_generic_to_shared(p);
}
__device__ __forceinline__ void ldsm_x4(uint32_t& r0, uint32_t& r1, uint32_t& r2, uint32_t& r3, uint32_t a) {
    asm volatile("ldmatrix.sync.aligned.m8n8.x4.shared.b16 {%0,%1,%2,%3}, [%4];"
                 : "=r"(r0), "=r"(r1), "=r"(r2), "=r"(r3) : "r"(a));
}
__device__ __forceinline__ void ldsm_x4_t(uint32_t& r0, uint32_t& r1, uint32_t& r2, uint32_t& r3, uint32_t a) {
    asm volatile("ldmatrix.sync.aligned.m8n8.x4.trans.shared.b16 {%0,%1,%2,%3}, [%4];"
                 : "=r"(r0), "=r"(r1), "=r"(r2), "=r"(r3) : "r"(a));
}
__device__ __forceinline__ void mma_bf16(float* c, const uint32_t* a, uint32_t b0, uint32_t b1) {
    asm volatile("mma.sync.aligned.m16n8k16.row.col.f32.bf16.bf16.f32 "
                 "{%0,%1,%2,%3}, {%4,%5,%6,%7}, {%8,%9}, {%0,%1,%2,%3};"
                 : "+f"(c[0]), "+f"(c[1]), "+f"(c[2]), "+f"(c[3])
                 : "r"(a[0]), "r"(a[1]), "r"(a[2]), "r"(a[3]), "r"(b0), "r"(b1));
}
__device__ __forceinline__ float ex2f(float x) {
    float y; asm("ex2.approx.ftz.f32 %0, %1;" : "=f"(y) : "f"(x)); return y;
}
__device__ __forceinline__ uint32_t packbf2(float lo, float hi) {
    __nv_bfloat162 t = __floats2bfloat162_rn(lo, hi);
    return *reinterpret_cast<uint32_t*>(&t);
}
__device__ __forceinline__ float sigmoidf_(float x) {
    float e = ex2f(-x * 1.4426950408889634f);
    return 1.0f / (1.0f + e);
}
#define STS128(addr, a_, b_, c_, d_) \
    asm volatile("st.shared.v4.b32 [%0], {%1,%2,%3,%4};" \
                 :: "r"(addr), "r"(a_), "r"(b_), "r"(c_), "r"(d_))
#define LDS128(a_, b_, c_, d_, addr) \
    asm volatile("ld.shared.v4.b32 {%0,%1,%2,%3}, [%4];" \
                 : "=r"(a_), "=r"(b_), "=r"(c_), "=r"(d_) : "r"(addr))
#define CP_ASYNC16(dst, src) \
    asm volatile("cp.async.cg.shared.global [%0], [%1], 16;" :: "r"(dst), "l"(src))
#define CP_COMMIT() asm volatile("cp.async.commit_group;" ::: "memory")
#define CP_WAIT0()  asm volatile("cp.async.wait_group 0;" ::: "memory")

// ---------------- pre-pass: fp32 -> bf16, pre-swizzled tile images ----------------
#define PREP_THREADS 256
#define PREP_BLOCKS  1024   // 262144 16B-units total (131072 per array)
__global__ __launch_bounds__(PREP_THREADS)
void convert_kv_kernel(const float* __restrict__ gk, const float* __restrict__ gv) {
    const uint32_t u = blockIdx.x * PREP_THREADS + threadIdx.x;
    const int isV = (u >> 17) & 1;
    const float* src = isV ? gv : gk;
    uint4* dst = isV ? g_vbf : g_kbf;
    const uint32_t r    = u & 131071u;
    const uint32_t g    = r >> 9;        // b*NT + t  (0..255); row base = g*64
    const uint32_t unit = r & 511u;
    const uint32_t row  = unit >> 3;
    const uint32_t cb   = unit & 7u;     // 8-col (16B) block
    const uint32_t sw   = SW128(row * 128u + cb * 16u);
    const float4* s4 = (const float4*)(src + ((size_t)(g * 64 + row)) * DIM + cb * 8);
    float4 f0 = s4[0], f1 = s4[1];
    uint4 o;
    o.x = packbf2(f0.x, f0.y);
    o.y = packbf2(f0.z, f0.w);
    o.z = packbf2(f1.x, f1.y);
    o.w = packbf2(f1.z, f1.w);
    dst[((size_t)g << 9) + (sw >> 4)] = o;
}

// ---------------- main kernel ----------------
__global__ __launch_bounds__(NTHREADS, 1)
void attn_fused_kernel(const float* __restrict__ gq,
                       float* __restrict__ gout) {
    // softmax denominators: [kv-half][row] (static smem)
    __shared__ __align__(16) float lpsh[2][BM];
    // dynamic smem: 4-stage K/V ring; first 16KB doubles as Q staging (pre-loop)
    // and O exchange (post-loop).
    extern __shared__ __align__(1024) __nv_bfloat16 sm_dyn[];

    const int tid = threadIdx.x;
    const int w   = tid >> 5;
    const int L   = tid & 31;
    const int wq  = w >> 1;      // q group: rows wq*16 .. wq*16+15
    const int wn  = w & 1;       // kv half: cols wn*32 .. wn*32+31
    const int b   = blockIdx.y;
    const int q0  = blockIdx.x * BM;

    const uint32_t dynB = smem_u32(sm_dyn);
    // stage s (0..3): K at dynB + s*8192, V at dynB + 32768 + s*8192

    // ---- Stage Q fp32 -> bf16 (pre-scaled), SW128 rows, in first 16KB ----
    {
        const int row  = tid >> 2;               // 0..127
        const int cblk = (tid & 3) * 16;         // 16 cols = 4 float4
        const float4* g = (const float4*)(gq + ((size_t)b * SQ + q0 + row) * DIM + cblk);
        float4 f0 = g[0], f1 = g[1], f2 = g[2], f3 = g[3];
        const uint32_t o0 = (uint32_t)(row * 128 + cblk * 2);
        STS128(dynB + SW128(o0),
               packbf2(f0.x * SCALE2, f0.y * SCALE2), packbf2(f0.z * SCALE2, f0.w * SCALE2),
               packbf2(f1.x * SCALE2, f1.y * SCALE2), packbf2(f1.z * SCALE2, f1.w * SCALE2));
        STS128(dynB + SW128(o0 + 16),
               packbf2(f2.x * SCALE2, f2.y * SCALE2), packbf2(f2.z * SCALE2, f2.w * SCALE2),
               packbf2(f3.x * SCALE2, f3.y * SCALE2), packbf2(f3.z * SCALE2, f3.w * SCALE2));
    }
    __syncthreads();

    // ---- Q fragments: 4 k-chunks of m16n8k16 A (16 regs) ----
    uint32_t aq[4][4];
    {
        const int rr = wq * 16 + ((L >> 3) & 1) * 8 + (L & 7);
        #pragma unroll
        for (int kc = 0; kc < 4; kc++) {
            const int cc = 16 * kc + (L >> 4) * 8;
            ldsm_x4(aq[kc][0], aq[kc][1], aq[kc][2], aq[kc][3],
                    dynB + SW128((uint32_t)(rr * 128 + cc * 2)));
        }
    }
    __syncthreads();   // Q staging consumed; region becomes K/V ring

    // ---- accumulators ----
    float oa[8][4];
    #pragma unroll
    for (int j = 0; j < 8; j++)
        #pragma unroll
        for (int i = 0; i < 4; i++) oa[j][i] = 0.0f;
    float lp0 = 0.0f, lp1 = 0.0f;

    // ---- cp.async tile copy: verbatim bytes (images are pre-swizzled) ----
    const uint4* kSrc0 = g_kbf + ((size_t)(b * NT) << 9) + tid;
    const uint4* vSrc0 = g_vbf + ((size_t)(b * NT) << 9) + tid;
    const uint32_t dOffT = (uint32_t)tid * 16u;
    #define CPA_TILE(t) do {                                                     \
        const uint32_t _s = (uint32_t)((t) & 3) * 8192u;                         \
        CP_ASYNC16(dynB + _s + dOffT,           (const void*)(kSrc0 + ((size_t)(t) << 9))); \
        CP_ASYNC16(dynB + 32768u + _s + dOffT,  (const void*)(vSrc0 + ((size_t)(t) << 9))); \
    } while (0)

    // ldmatrix lane-address pieces
    const int kq_r  = (L & 7);
    const int kq_c8 = (L >> 3) * 8;
    const int v_r   = ((L >> 3) & 1) * 8 + (L & 7);
    const int v_c8  = (L >> 4) * 8;

    // ---- prologue: issue tiles 0,1 ----
    CPA_TILE(0);
    CPA_TILE(1);
    CP_COMMIT();

    // ---- main loop: single body, barrier + cp.async issue every 2 tiles ----
    #pragma unroll 1
    for (int n = 0; n < NT; n++) {
        if ((n & 1) == 0) {
            CP_WAIT0();        // this thread's copies for tiles n, n+1 complete
            __syncthreads();   // all threads' copies visible; prev pair stages free
            if (n + 2 < NT) {
                CPA_TILE(n + 2);
                if (n + 3 < NT) CPA_TILE(n + 3);
                CP_COMMIT();
            }
        }
        const uint32_t skB = dynB + (uint32_t)(n & 3) * 8192u;
        const uint32_t svB = skB + 32768u;

        // ---- S = Q @ K^T : 16q x 32kv per warp ----
        float sc[4][4];
        #pragma unroll
        for (int j = 0; j < 4; j++)
            #pragma unroll
            for (int i = 0; i < 4; i++) sc[j][i] = 0.0f;

        #pragma unroll
        for (int j = 0; j < 4; j++) {
            const int rr = wn * 32 + 8 * j + kq_r;
            #pragma unroll
            for (int kc2 = 0; kc2 < 2; kc2++) {
                uint32_t b0, b1, b2, b3;
                const int cc = 32 * kc2 + kq_c8;
                ldsm_x4(b0, b1, b2, b3, skB + SW128((uint32_t)(rr * 128 + cc * 2)));
                mma_bf16(sc[j], aq[2 * kc2],     b0, b1);
                mma_bf16(sc[j], aq[2 * kc2 + 1], b2, b3);
            }
        }

        // ---- softmax: p = 2^s; accumulate denominators; pack P as A-fragments ----
        uint32_t ap[2][4];
        #pragma unroll
        for (int j = 0; j < 4; j++) {
            float p0 = ex2f(sc[j][0]);
            float p1 = ex2f(sc[j][1]);
            float p2 = ex2f(sc[j][2]);
            float p3 = ex2f(sc[j][3]);
            lp0 += p0 + p1;
            lp1 += p2 + p3;
            const int kcp = j >> 1;
            if ((j & 1) == 0) {
                ap[kcp][0] = packbf2(p0, p1);
                ap[kcp][1] = packbf2(p2, p3);
            } else {
                ap[kcp][2] = packbf2(p0, p1);
                ap[kcp][3] = packbf2(p2, p3);
            }
        }

        // ---- O += P @ V : 16q x 64d per warp over its 32 kv rows ----
        #pragma unroll
        for (int kcp = 0; kcp < 2; kcp++) {
            const int rr = wn * 32 + 16 * kcp + v_r;
            #pragma unroll
            for (int j2 = 0; j2 < 8; j2 += 2) {
                uint32_t b0, b1, b2, b3;
                const int cc = 8 * j2 + v_c8;
                ldsm_x4_t(b0, b1, b2, b3, svB + SW128((uint32_t)(rr * 128 + cc * 2)));
                mma_bf16(oa[j2],     ap[kcp], b0, b1);
                mma_bf16(oa[j2 + 1], ap[kcp], b2, b3);
            }
        }
    }

    // ---- softmax denominators: quad-reduce; publish per (half,row) ----
    lp0 += __shfl_xor_sync(0xFFFFFFFFu, lp0, 1);
    lp0 += __shfl_xor_sync(0xFFFFFFFFu, lp0, 2);
    lp1 += __shfl_xor_sync(0xFFFFFFFFu, lp1, 1);
    lp1 += __shfl_xor_sync(0xFFFFFFFFu, lp1, 2);
    __syncthreads();   // all warps done with the ring
    if ((L & 3) == 0) {
        const int rbase = wq * 16 + (L >> 2);
        lpsh[wn][rbase]     = lp0;
        lpsh[wn][rbase + 8] = lp1;
    }

    // ---- O exchange: warp (wq,wn) keeps d-half wn, ships d-half 1-wn ----
    {
        const int ship = 1 - wn;
        const uint32_t slot = dynB + (uint32_t)(wq * 2 + ship) * 2048;
        #pragma unroll
        for (int jp = 0; jp < 4; jp++) {
            const int j = ship * 4 + jp;
            STS128(slot + (uint32_t)(jp * 32 + L) * 16,
                   __float_as_uint(oa[j][0]), __float_as_uint(oa[j][1]),
                   __float_as_uint(oa[j][2]), __float_as_uint(oa[j][3]));
        }
    }
    __syncthreads();
    {
        const uint32_t slot = dynB + (uint32_t)(wq * 2 + wn) * 2048;
        #pragma unroll
        for (int jp = 0; jp < 4; jp++) {
            const int j = wn * 4 + jp;
            uint32_t x, y, z, u;
            LDS128(x, y, z, u, slot + (uint32_t)(jp * 32 + L) * 16);
            oa[j][0] += __uint_as_float(x);
            oa[j][1] += __uint_as_float(y);
            oa[j][2] += __uint_as_float(z);
            oa[j][3] += __uint_as_float(u);
        }
    }

    // ---- epilogue: warp (wq,wn) owns rows wq*16+{0..15}, d-cols wn*32..+31 ----
    const int lr0 = wq * 16 + (L >> 2);
    const float inv0 = 1.0f / (lpsh[0][lr0] + lpsh[1][lr0]);
    const float inv1 = 1.0f / (lpsh[0][lr0 + 8] + lpsh[1][lr0 + 8]);

    const int r0 = q0 + lr0;
    const int r1 = r0 + 8;
    const float* q0p = gq + ((size_t)b * SQ + r0) * DIM;
    const float* q1p = gq + ((size_t)b * SQ + r1) * DIM;
    float* o0p = gout + ((size_t)b * SQ + r0) * DIM;
    float* o1p = gout + ((size_t)b * SQ + r1) * DIM;

    #pragma unroll
    for (int jp = 0; jp < 4; jp++) {
        const int j  = wn * 4 + jp;
        const int d0 = 8 * j + 2 * (L & 3);
        float2 qa = *(const float2*)(q0p + d0);
        float2 qb = *(const float2*)(q1p + d0);
        float o0 = oa[j][0] * inv0 + qa.x;
        float o1 = oa[j][1] * inv0 + qa.y;
        float o2 = oa[j][2] * inv1 + qb.x;
        float o3 = oa[j][3] * inv1 + qb.y;
        #pragma unroll
        for (int it = 0; it < 3; it++) {
            o0 = sigmoidf_(o0 + 2.0f * qa.x);
            o1 = sigmoidf_(o1 + 2.0f * qa.y);
            o2 = sigmoidf_(o2 + 2.0f * qb.x);
            o3 = sigmoidf_(o3 + 2.0f * qb.y);
            o0 = fminf(fmaxf(o0, 0.0f), 1.0f);
            o1 = fminf(fmaxf(o1, 0.0f), 1.0f);
            o2 = fminf(fmaxf(o2, 0.0f), 1.0f);
            o3 = fminf(fmaxf(o3, 0.0f), 1.0f);
        }
        *(float2*)(o0p + d0) = make_float2(o0, o1);
        *(float2*)(o1p + d0) = make_float2(o2, o3);
    }
}

extern "C" void kernel_launch(void* const* d_in, const int* in_sizes, int n_in,
                              void* d_out, int out_size) {
    const float* q = (const float*)d_in[0];
    const float* k = (const float*)d_in[1];
    const float* v = (const float*)d_in[2];
    float* out = (float*)d_out;

    // idempotent; needed for 64KB dynamic smem (static limit is 48KB)
    cudaFuncSetAttribute(attn_fused_kernel,
                         cudaFuncAttributeMaxDynamicSharedMemorySize, SMEM_BYTES);

    convert_kv_kernel<<<PREP_BLOCKS, PREP_THREADS>>>(k, v);

    dim3 grid(SQ / BM, BATCH);
    attn_fused_kernel<<<grid, NTHREADS, SMEM_BYTES>>>(q, out);
}